// round 5
// baseline (speedup 1.0000x reference)
#include <cuda_runtime.h>
#include <stdint.h>
#include <math.h>

#define THREADS 128
#define CPT 128                        // cells per tile (= threads)
#define STAGES 3
#define NB 4096
#define TOTAL_CELLS (NB * 14 * 14)     // 802816
#define NTILES (TOTAL_CELLS / CPT)     // 6272
#define BLOCKS_PER_SM 2
#define GRID (148 * BLOCKS_PER_SM)     // 296 persistent blocks
#define TILE_FLOATS (CPT * 30)         // 3840 floats = 15360 B per array
#define TILE_F4 (TILE_FLOATS / 4)      // 960
#define SMEM_BYTES (STAGES * 2 * TILE_FLOATS * 4)   // 92160 B

__device__ double g_acc = 0.0;
__device__ unsigned int g_ticket = 0u;

__device__ __forceinline__ void cp16(uint32_t s, const float4* g) {
    asm volatile("cp.async.cg.shared.global [%0], [%1], 16;" :: "r"(s), "l"(g));
}
__device__ __forceinline__ void cp_commit() {
    asm volatile("cp.async.commit_group;" ::: "memory");
}

extern __shared__ float smem_dyn[];

__global__ void __launch_bounds__(THREADS)
yolo_loss_kernel(const float* __restrict__ pred, const float* __restrict__ target,
                 float* __restrict__ out) {
    __shared__ float wsum[THREADS / 32];

    const int tid = threadIdx.x;
    const uint32_t s_base = (uint32_t)__cvta_generic_to_shared(smem_dyn);
    // layout: buffer i: [pred tile | target tile], stride 2*TILE_FLOATS floats
    const uint32_t buf_bytes = 2u * TILE_FLOATS * 4u;

    // ---- issue cp.async loads for one tile into buffer `buf` ----
    auto issue = [&](int tile, int buf) {
        const float4* gp = (const float4*)pred + (size_t)tile * TILE_F4;
        const float4* gt = (const float4*)target + (size_t)tile * TILE_F4;
        const uint32_t dp = s_base + (uint32_t)buf * buf_bytes;
        const uint32_t dt = dp + (uint32_t)(TILE_FLOATS * 4);
        #pragma unroll
        for (int k = 0; k < 7; k++) {
            const int i = tid + k * THREADS;
            cp16(dp + i * 16, gp + i);
            cp16(dt + i * 16, gt + i);
        }
        {   // 960 = 7*128 + 64: tail for half the threads
            const int i = tid + 7 * THREADS;
            if (i < TILE_F4) { cp16(dp + i * 16, gp + i); cp16(dt + i * 16, gt + i); }
        }
    };

    // ---- prologue: 2 tiles in flight ----
    int t = blockIdx.x;
    issue(t, 0);
    cp_commit();
    if (t + GRID < NTILES) issue(t + GRID, 1);
    cp_commit();   // group committed even if empty (uniform accounting)

    float acc = 0.0f;
    int b = 0;
    while (t < NTILES) {
        const int t2 = t + 2 * GRID;
        int b2 = b + 2; if (b2 >= STAGES) b2 -= STAGES;
        if (t2 < NTILES) issue(t2, b2);
        cp_commit();                       // pending groups: 3
        asm volatile("cp.async.wait_group 2;" ::: "memory");   // oldest (tile t) done
        __syncthreads();                   // visibility of all threads' copies

        // ---- per-cell loss from smem buffer b ----
        {
            const float* p  = smem_dyn + (size_t)b * 2 * TILE_FLOATS + tid * 30;
            const float* tt = p + TILE_FLOATS;

            const float t4 = tt[4];
            const float objm   = (t4 > 0.0f) ? 1.0f : 0.0f;
            const float noobjm = (t4 == 0.0f) ? 1.0f : 0.0f;

            // no-object confidence loss (both box slots)
            const float d4 = p[4] - t4;
            const float d9 = p[9] - tt[9];
            const float l_noobj = d4 * d4 + d9 * d9;

            // target box 0 corners
            const float inv_s = 1.0f / 14.0f;
            const float txc = tt[0] * inv_s, tyc = tt[1] * inv_s;
            const float thw = 0.5f * tt[2], thh = 0.5f * tt[3];
            const float tx0 = txc - thw, ty0 = tyc - thh;
            const float tx1 = txc + thw, ty1 = tyc + thh;
            const float area_t = (tx1 - tx0) * (ty1 - ty0);

            float iou[2];
            #pragma unroll
            for (int bb = 0; bb < 2; bb++) {
                const float* pb = p + 5 * bb;
                const float pxc = pb[0] * inv_s, pyc = pb[1] * inv_s;
                const float phw = 0.5f * pb[2], phh = 0.5f * pb[3];
                const float px0 = pxc - phw, py0 = pyc - phh;
                const float px1 = pxc + phw, py1 = pyc + phh;
                const float area_p = (px1 - px0) * (py1 - py0);
                const float iw = fmaxf(fminf(px1, tx1) - fmaxf(px0, tx0), 0.0f);
                const float ih = fmaxf(fminf(py1, ty1) - fmaxf(py0, ty0), 0.0f);
                const float inter = iw * ih;
                iou[bb] = inter / (area_p + area_t - inter);
            }

            // responsible box: first-max on tie (jnp.argmax semantics)
            const int roff = (iou[1] > iou[0]) ? 5 : 0;
            const float max_iou = fmaxf(iou[0], iou[1]);

            const float* pr = p + roff;
            const float* tr = tt + roff;

            const float dx = pr[0] - tr[0];
            const float dy = pr[1] - tr[1];
            const float l_xy = dx * dx + dy * dy;

            const float dw = sqrtf(pr[2]) - sqrtf(tr[2]);
            const float dh = sqrtf(pr[3]) - sqrtf(tr[3]);
            const float l_wh = dw * dw + dh * dh;

            const float dob = pr[4] - max_iou;
            const float l_obj = dob * dob;

            float l_cls = 0.0f;
            #pragma unroll
            for (int c = 0; c < 20; c++) {
                const float dc = p[10 + c] - tt[10 + c];
                l_cls = fmaf(dc, dc, l_cls);
            }

            acc += objm * (5.0f * (l_xy + l_wh) + l_obj + l_cls)
                 + 0.5f * noobjm * l_noobj;
        }

        __syncthreads();       // all done reading buf b before it is re-issued
        b += 1; if (b >= STAGES) b = 0;
        t += GRID;
    }

    // ---- block reduction + global accumulate ----
    float v = acc;
    #pragma unroll
    for (int o = 16; o > 0; o >>= 1) v += __shfl_down_sync(0xFFFFFFFFu, v, o);
    if ((tid & 31) == 0) wsum[tid >> 5] = v;
    __syncthreads();

    if (tid == 0) {
        const float s = wsum[0] + wsum[1] + wsum[2] + wsum[3];
        atomicAdd(&g_acc, (double)s);
        __threadfence();
        const unsigned int ticket = atomicAdd(&g_ticket, 1u);
        if (ticket == (unsigned int)(GRID - 1)) {
            const double total = g_acc;
            out[0] = (float)(total * (1.0 / (double)NB));
            g_acc = 0.0;       // reset for next graph replay
            __threadfence();
            g_ticket = 0u;
        }
    }
}

extern "C" void kernel_launch(void* const* d_in, const int* in_sizes, int n_in,
                              void* d_out, int out_size) {
    const float* pred = (const float*)d_in[0];
    const float* target = (const float*)d_in[1];
    float* out = (float*)d_out;

    static bool attr_set = false;
    if (!attr_set) {
        cudaFuncSetAttribute(yolo_loss_kernel,
                             cudaFuncAttributeMaxDynamicSharedMemorySize, SMEM_BYTES);
        attr_set = true;
    }
    yolo_loss_kernel<<<GRID, THREADS, SMEM_BYTES>>>(pred, target, out);
}

// round 6
// speedup vs baseline: 1.1213x; 1.1213x over previous
#include <cuda_runtime.h>
#include <stdint.h>
#include <math.h>

#define THREADS 128
#define CPT 64                         // cells per tile
#define NB 4096
#define TOTAL_CELLS (NB * 14 * 14)     // 802816
#define NTILES (TOTAL_CELLS / CPT)     // 12544
#define GRID (148 * 7)                 // 1036 persistent blocks
#define TILE_FLOATS (CPT * 30)         // 1920 floats = 7680 B per array
#define TILE_F4 (TILE_FLOATS / 4)      // 480

__device__ double g_acc = 0.0;
__device__ unsigned int g_ticket = 0u;

__device__ __forceinline__ void cp16(uint32_t s, const float4* g) {
    asm volatile("cp.async.cg.shared.global [%0], [%1], 16;" :: "r"(s), "l"(g));
}
__device__ __forceinline__ void cp_commit() {
    asm volatile("cp.async.commit_group;" ::: "memory");
}

__global__ void __launch_bounds__(THREADS)
yolo_loss_kernel(const float* __restrict__ pred, const float* __restrict__ target,
                 float* __restrict__ out) {
    __shared__ float sp[2][TILE_FLOATS];
    __shared__ float st[2][TILE_FLOATS];
    __shared__ float wsum[THREADS / 32];

    const int tid = threadIdx.x;
    const uint32_t sp0 = (uint32_t)__cvta_generic_to_shared(&sp[0][0]);
    const uint32_t st0 = (uint32_t)__cvta_generic_to_shared(&st[0][0]);
    const uint32_t buf_bytes = (uint32_t)(TILE_FLOATS * 4);

    // ---- issue cp.async loads for one tile into buffer `buf` ----
    // 480 float4 per array over 128 threads: 3 full strides + half-tail
    auto issue = [&](int tile, int buf) {
        const float4* gp = (const float4*)pred + (size_t)tile * TILE_F4;
        const float4* gt = (const float4*)target + (size_t)tile * TILE_F4;
        const uint32_t dp = sp0 + (uint32_t)buf * buf_bytes;
        const uint32_t dt = st0 + (uint32_t)buf * buf_bytes;
        #pragma unroll
        for (int k = 0; k < 3; k++) {
            const int i = tid + k * THREADS;
            cp16(dp + i * 16, gp + i);
            cp16(dt + i * 16, gt + i);
        }
        {   // 480 = 3*128 + 96
            const int i = tid + 3 * THREADS;
            if (i < TILE_F4) { cp16(dp + i * 16, gp + i); cp16(dt + i * 16, gt + i); }
        }
    };

    // ---- prologue: 2 tiles in flight ----
    int t = blockIdx.x;
    issue(t, 0);
    cp_commit();
    if (t + GRID < NTILES) issue(t + GRID, 1);
    cp_commit();   // committed even if empty (uniform group accounting)

    float acc = 0.0f;
    int b = 0;
    while (t < NTILES) {
        asm volatile("cp.async.wait_group 1;" ::: "memory");   // oldest (tile t) done
        __syncthreads();

        // ---- per-cell loss from smem buffer b (threads 0..63) ----
        if (tid < CPT) {
            const float* p  = &sp[b][tid * 30];
            const float* tt = &st[b][tid * 30];

            const float t4 = tt[4];
            const float objm   = (t4 > 0.0f) ? 1.0f : 0.0f;
            const float noobjm = (t4 == 0.0f) ? 1.0f : 0.0f;

            const float d4 = p[4] - t4;
            const float d9 = p[9] - tt[9];
            const float l_noobj = d4 * d4 + d9 * d9;

            const float inv_s = 1.0f / 14.0f;
            const float txc = tt[0] * inv_s, tyc = tt[1] * inv_s;
            const float thw = 0.5f * tt[2], thh = 0.5f * tt[3];
            const float tx0 = txc - thw, ty0 = tyc - thh;
            const float tx1 = txc + thw, ty1 = tyc + thh;
            const float area_t = (tx1 - tx0) * (ty1 - ty0);

            float iou[2];
            #pragma unroll
            for (int bb = 0; bb < 2; bb++) {
                const float* pb = p + 5 * bb;
                const float pxc = pb[0] * inv_s, pyc = pb[1] * inv_s;
                const float phw = 0.5f * pb[2], phh = 0.5f * pb[3];
                const float px0 = pxc - phw, py0 = pyc - phh;
                const float px1 = pxc + phw, py1 = pyc + phh;
                const float area_p = (px1 - px0) * (py1 - py0);
                const float iw = fmaxf(fminf(px1, tx1) - fmaxf(px0, tx0), 0.0f);
                const float ih = fmaxf(fminf(py1, ty1) - fmaxf(py0, ty0), 0.0f);
                const float inter = iw * ih;
                iou[bb] = inter / (area_p + area_t - inter);
            }

            // responsible box: first-max on tie (jnp.argmax semantics)
            const int roff = (iou[1] > iou[0]) ? 5 : 0;
            const float max_iou = fmaxf(iou[0], iou[1]);

            const float* pr = p + roff;
            const float* tr = tt + roff;

            const float dx = pr[0] - tr[0];
            const float dy = pr[1] - tr[1];
            const float l_xy = dx * dx + dy * dy;

            const float dw = sqrtf(pr[2]) - sqrtf(tr[2]);
            const float dh = sqrtf(pr[3]) - sqrtf(tr[3]);
            const float l_wh = dw * dw + dh * dh;

            const float dob = pr[4] - max_iou;
            const float l_obj = dob * dob;

            float l_cls = 0.0f;
            #pragma unroll
            for (int c = 0; c < 20; c++) {
                const float dc = p[10 + c] - tt[10 + c];
                l_cls = fmaf(dc, dc, l_cls);
            }

            acc += objm * (5.0f * (l_xy + l_wh) + l_obj + l_cls)
                 + 0.5f * noobjm * l_noobj;
        }

        __syncthreads();      // all reads of buffer b complete before re-issue
        const int t2 = t + 2 * GRID;
        if (t2 < NTILES) issue(t2, b);
        cp_commit();          // keep exactly one group per pipeline slot
        b ^= 1;
        t += GRID;
    }

    // ---- block reduction + global accumulate ----
    float v = acc;
    #pragma unroll
    for (int o = 16; o > 0; o >>= 1) v += __shfl_down_sync(0xFFFFFFFFu, v, o);
    if ((tid & 31) == 0) wsum[tid >> 5] = v;
    __syncthreads();

    if (tid == 0) {
        const float s = wsum[0] + wsum[1] + wsum[2] + wsum[3];
        atomicAdd(&g_acc, (double)s);
        __threadfence();
        const unsigned int ticket = atomicAdd(&g_ticket, 1u);
        if (ticket == (unsigned int)(GRID - 1)) {
            const double total = g_acc;
            out[0] = (float)(total * (1.0 / (double)NB));
            g_acc = 0.0;      // reset for next graph replay
            __threadfence();
            g_ticket = 0u;
        }
    }
}

extern "C" void kernel_launch(void* const* d_in, const int* in_sizes, int n_in,
                              void* d_out, int out_size) {
    const float* pred = (const float*)d_in[0];
    const float* target = (const float*)d_in[1];
    float* out = (float*)d_out;
    yolo_loss_kernel<<<GRID, THREADS>>>(pred, target, out);
}